// round 7
// baseline (speedup 1.0000x reference)
#include <cuda_runtime.h>
#include <cuda_bf16.h>
#include <math.h>
#include <stdint.h>

// Problem constants
#define BB   4
#define TT   512
#define HH   2048
#define VV   32000
#define BT   (BB*TT)          // 2048 rows
#define BETA_C   0.1f
#define EPS_LO_C 0.2f
#define EPS_HI_C 0.2f

// GEMM tiling (Ampere-style mma.sync path; tcgen05 not available on this target)
#define BM 128
#define BN 128
#define KC 32                  // K chunk in bf16 elems
#define NCHUNK (HH/KC)         // 64
#define NST 2                  // pipeline stages (2 -> 80KB smem -> 2 CTAs/SM)
#define PITCH 80               // smem row pitch bytes (conflict-free for LDSM)
#define AHI_OFF 0
#define ALO_OFF 10240
#define BHI_OFF 20480
#define BLO_OFF 30720
#define STAGE_BYTES 40960
#define SMEM_DYN (NST*STAGE_BYTES)   // 81920 -> two CTAs per SM

// ---------------- scratch (static device globals; no allocations) ----------------
__device__ float              g_sum_pol[BT];
__device__ float              g_sum_ref[BT];
__device__ unsigned long long g_pack[BT];
__device__ float              g_pdot[BT];
__device__ float              g_rdot[BT];
__device__ __align__(1024) __nv_bfloat16 g_xh[BT*HH];
__device__ __align__(1024) __nv_bfloat16 g_xl[BT*HH];
__device__ __align__(1024) __nv_bfloat16 g_wh[(size_t)VV*HH];
__device__ __align__(1024) __nv_bfloat16 g_wl[(size_t)VV*HH];
__device__ __align__(1024) __nv_bfloat16 g_rxh[BT*HH];
__device__ __align__(1024) __nv_bfloat16 g_rxl[BT*HH];
__device__ __align__(1024) __nv_bfloat16 g_rwh[(size_t)VV*HH];
__device__ __align__(1024) __nv_bfloat16 g_rwl[(size_t)VV*HH];

// ---------------- PTX helpers (all sm_80-class; no 'a' features) ----------------
__device__ __forceinline__ uint32_t s2u(const void* p) {
    uint32_t a;
    asm("{ .reg .u64 t; cvta.to.shared.u64 t, %1; cvt.u32.u64 %0, t; }" : "=r"(a) : "l"(p));
    return a;
}
__device__ __forceinline__ void cpasync16(uint32_t s, const void* g) {
    asm volatile("cp.async.cg.shared.global [%0], [%1], 16;" :: "r"(s), "l"(g) : "memory");
}
__device__ __forceinline__ void cp_commit() {
    asm volatile("cp.async.commit_group;" ::: "memory");
}
template <int N>
__device__ __forceinline__ void cp_wait() {
    asm volatile("cp.async.wait_group %0;" :: "n"(N) : "memory");
}
__device__ __forceinline__ void ldsm4(uint32_t* r, uint32_t a) {
    asm volatile("ldmatrix.sync.aligned.m8n8.x4.shared.b16 {%0,%1,%2,%3}, [%4];"
                 : "=r"(r[0]), "=r"(r[1]), "=r"(r[2]), "=r"(r[3]) : "r"(a));
}
__device__ __forceinline__ void mma16816(float* d, const uint32_t* a, const uint32_t* b) {
    asm volatile(
        "mma.sync.aligned.m16n8k16.row.col.f32.bf16.bf16.f32 "
        "{%0,%1,%2,%3}, {%4,%5,%6,%7}, {%8,%9}, {%0,%1,%2,%3};"
        : "+f"(d[0]), "+f"(d[1]), "+f"(d[2]), "+f"(d[3])
        : "r"(a[0]), "r"(a[1]), "r"(a[2]), "r"(a[3]), "r"(b[0]), "r"(b[1]));
}
__device__ __forceinline__ unsigned fkey(float f) {
    unsigned u = __float_as_uint(f);
    return (u & 0x80000000u) ? ~u : (u | 0x80000000u);
}
// FMA-only exp (no MUFU): rel err ~2.4e-6 on our logit range
__device__ __forceinline__ float fexp(float x) {
    float t = x * 1.4426950408889634f;
    float r = rintf(t);
    float u = (t - r) * 0.6931471805599453f;
    float p = 8.3333333e-3f;
    p = fmaf(p, u, 4.1666667e-2f);
    p = fmaf(p, u, 1.6666667e-1f);
    p = fmaf(p, u, 0.5f);
    p = fmaf(p, u, 1.0f);
    p = fmaf(p, u, 1.0f);
    int e = (int)r;
    return p * __int_as_float((e + 127) << 23);
}

// ---------------- init ----------------
__global__ void init_kernel() {
    int i = blockIdx.x * blockDim.x + threadIdx.x;
    if (i < BT) {
        g_sum_pol[i] = 0.0f;
        g_sum_ref[i] = 0.0f;
        g_pack[i] = 0ull;
    }
}

// ---------------- fp32 -> bf16 hi/lo split ----------------
__global__ void convert_kernel(const float* __restrict__ src,
                               __nv_bfloat16* __restrict__ hi,
                               __nv_bfloat16* __restrict__ lo, int n4) {
    int i = blockIdx.x * blockDim.x + threadIdx.x;
    if (i >= n4) return;
    float4 v = ((const float4*)src)[i];
    __nv_bfloat16 h0 = __float2bfloat16(v.x);
    __nv_bfloat16 h1 = __float2bfloat16(v.y);
    __nv_bfloat16 h2 = __float2bfloat16(v.z);
    __nv_bfloat16 h3 = __float2bfloat16(v.w);
    __nv_bfloat16 l0 = __float2bfloat16(v.x - __bfloat162float(h0));
    __nv_bfloat16 l1 = __float2bfloat16(v.y - __bfloat162float(h1));
    __nv_bfloat16 l2 = __float2bfloat16(v.z - __bfloat162float(h2));
    __nv_bfloat16 l3 = __float2bfloat16(v.w - __bfloat162float(h3));
    uint2 uh, ul;
    uh.x = (uint32_t)__bfloat16_as_ushort(h0) | ((uint32_t)__bfloat16_as_ushort(h1) << 16);
    uh.y = (uint32_t)__bfloat16_as_ushort(h2) | ((uint32_t)__bfloat16_as_ushort(h3) << 16);
    ul.x = (uint32_t)__bfloat16_as_ushort(l0) | ((uint32_t)__bfloat16_as_ushort(l1) << 16);
    ul.y = (uint32_t)__bfloat16_as_ushort(l2) | ((uint32_t)__bfloat16_as_ushort(l3) << 16);
    ((uint2*)hi)[i] = uh;
    ((uint2*)lo)[i] = ul;
}

// ---------------- bf16x3 tensor-core GEMM + fused softmax-stats ----------------
// blockIdx.z = 0: policy (argmax on), 1: reference
__global__ void __launch_bounds__(256, 2)
gemm_mma(const __nv_bfloat16* __restrict__ pAh, const __nv_bfloat16* __restrict__ pAl,
         const __nv_bfloat16* __restrict__ pBh, const __nv_bfloat16* __restrict__ pBl,
         const __nv_bfloat16* __restrict__ rAh, const __nv_bfloat16* __restrict__ rAl,
         const __nv_bfloat16* __restrict__ rBh, const __nv_bfloat16* __restrict__ rBl,
         float* __restrict__ sum_pol, float* __restrict__ sum_ref,
         unsigned long long* __restrict__ packed) {
    extern __shared__ char smem[];
    const uint32_t sb = s2u(smem);
    const int tid  = threadIdx.x;
    const int lane = tid & 31;
    const int wid  = tid >> 5;
    const int wm   = wid >> 2;          // 0..1  (64-row slab)
    const int wn   = wid & 3;           // 0..3  (32-col slab)
    const int m0 = blockIdx.x * BM;
    const int n0 = blockIdx.y * BN;
    const int zz = blockIdx.z;          // 0 = policy, 1 = reference

    const __nv_bfloat16* Ah = zz ? rAh : pAh;
    const __nv_bfloat16* Al = zz ? rAl : pAl;
    const __nv_bfloat16* Bh = zz ? rBh : pBh;
    const __nv_bfloat16* Bl = zz ? rBl : pBl;
    float* sumexp = zz ? sum_ref : sum_pol;
    const int do_max = (zz == 0);

    float acc[4][4][4];
#pragma unroll
    for (int mt = 0; mt < 4; ++mt)
#pragma unroll
        for (int nt = 0; nt < 4; ++nt)
#pragma unroll
            for (int j = 0; j < 4; ++j) acc[mt][nt][j] = 0.0f;

    // per-thread load coords: chunks c = tid, tid+256 of 512 16B-chunks per matrix
    const int c0r = tid >> 2,  c0c = tid & 3;
    const int c1r = (tid + 256) >> 2, c1c = tid & 3;

    auto load_stage = [&](int st, int k0) {
        uint32_t stb = sb + st * STAGE_BYTES;
        {
            uint32_t so = c0r * PITCH + c0c * 16;
            size_t ga = (size_t)(m0 + c0r) * HH + k0 + c0c * 8;
            size_t gb = (size_t)(n0 + c0r) * HH + k0 + c0c * 8;
            cpasync16(stb + AHI_OFF + so, Ah + ga);
            cpasync16(stb + ALO_OFF + so, Al + ga);
            cpasync16(stb + BHI_OFF + so, Bh + gb);
            cpasync16(stb + BLO_OFF + so, Bl + gb);
        }
        {
            uint32_t so = c1r * PITCH + c1c * 16;
            size_t ga = (size_t)(m0 + c1r) * HH + k0 + c1c * 8;
            size_t gb = (size_t)(n0 + c1r) * HH + k0 + c1c * 8;
            cpasync16(stb + AHI_OFF + so, Ah + ga);
            cpasync16(stb + ALO_OFF + so, Al + ga);
            cpasync16(stb + BHI_OFF + so, Bh + gb);
            cpasync16(stb + BLO_OFF + so, Bl + gb);
        }
    };

    // prologue: chunk 0 -> stage 0
    load_stage(0, 0);
    cp_commit();

    const int arow_base = wm * 64 + (lane & 15);
    const int a_half    = (lane >> 4);
    // B ldsm4: lanes 0-7 -> (n0-7,k chunk0), 8-15 -> (n0-7,k chunk1),
    //          16-23 -> (n8-15,k chunk0), 24-31 -> (n8-15,k chunk1)
    const int brow_base = wn * 32 + ((lane >> 4) & 1) * 8 + (lane & 7);
    const int bksel     = (lane >> 3) & 1;

    for (int c = 0; c < NCHUNK; ++c) {
        // prefetch next chunk into the other stage (drained in iteration c-1)
        if (c + 1 < NCHUNK) load_stage((c + 1) & 1, (c + 1) * KC);
        cp_commit();
        cp_wait<1>();            // stage c resident (c+1 still in flight)
        __syncthreads();

        uint32_t stb = sb + (c & 1) * STAGE_BYTES;
#pragma unroll
        for (int ks = 0; ks < 2; ++ks) {
            uint32_t acol = (ks * 2 + a_half) * 16;
            uint32_t bcol = (ks * 2 + bksel) * 16;
            // staged loads to limit live fragment registers:
            uint32_t ah[4][4], bh[2][4];
#pragma unroll
            for (int mt = 0; mt < 4; ++mt)
                ldsm4(ah[mt], stb + AHI_OFF + (uint32_t)(arow_base + mt * 16) * PITCH + acol);
#pragma unroll
            for (int p = 0; p < 2; ++p)
                ldsm4(bh[p], stb + BHI_OFF + (uint32_t)(brow_base + p * 16) * PITCH + bcol);
#pragma unroll
            for (int mt = 0; mt < 4; ++mt)
#pragma unroll
                for (int nt = 0; nt < 4; ++nt)
                    mma16816(acc[mt][nt], ah[mt], &bh[nt >> 1][(nt & 1) * 2]);

            uint32_t bl[2][4];
#pragma unroll
            for (int p = 0; p < 2; ++p)
                ldsm4(bl[p], stb + BLO_OFF + (uint32_t)(brow_base + p * 16) * PITCH + bcol);
#pragma unroll
            for (int mt = 0; mt < 4; ++mt)
#pragma unroll
                for (int nt = 0; nt < 4; ++nt)
                    mma16816(acc[mt][nt], ah[mt], &bl[nt >> 1][(nt & 1) * 2]);

            // third product in two halves to cap live registers
#pragma unroll
            for (int h2 = 0; h2 < 2; ++h2) {
                uint32_t al[2][4];
#pragma unroll
                for (int m2 = 0; m2 < 2; ++m2)
                    ldsm4(al[m2], stb + ALO_OFF
                          + (uint32_t)(arow_base + (h2 * 2 + m2) * 16) * PITCH + acol);
#pragma unroll
                for (int m2 = 0; m2 < 2; ++m2)
#pragma unroll
                    for (int nt = 0; nt < 4; ++nt)
                        mma16816(acc[h2 * 2 + m2][nt], al[m2], &bh[nt >> 1][(nt & 1) * 2]);
            }
        }
        __syncthreads();         // all warps done with stage c before iter c+1 overwrites it
    }

    // ---- epilogue: row-wise sum(exp) + argmax, quad shfl reduce, atomics ----
#pragma unroll
    for (int mt = 0; mt < 4; ++mt) {
#pragma unroll
        for (int half = 0; half < 2; ++half) {
            int row = m0 + wm * 64 + mt * 16 + (lane >> 2) + half * 8;
            float s = 0.0f;
            float vmax = -3.402823466e+38f;
            unsigned am = 0;
#pragma unroll
            for (int nt = 0; nt < 4; ++nt)
#pragma unroll
                for (int j = 0; j < 2; ++j) {
                    float v = acc[mt][nt][half * 2 + j];
                    s += fexp(v);
                    unsigned col = (unsigned)(n0 + wn * 32 + nt * 8 + (lane & 3) * 2 + j);
                    if (v > vmax) { vmax = v; am = col; }
                }
#pragma unroll
            for (int m = 1; m < 4; m <<= 1) {
                s += __shfl_xor_sync(0xFFFFFFFFu, s, m);
                float ov = __shfl_xor_sync(0xFFFFFFFFu, vmax, m);
                unsigned oa = __shfl_xor_sync(0xFFFFFFFFu, am, m);
                if (ov > vmax || (ov == vmax && oa < am)) { vmax = ov; am = oa; }
            }
            if ((lane & 3) == 0) {
                atomicAdd(&sumexp[row], s);
                if (do_max) {
                    unsigned long long p = ((unsigned long long)fkey(vmax) << 32)
                                         | (unsigned long long)(0xFFFFFFFFu - am);
                    atomicMax(&packed[row], p);
                }
            }
        }
    }
}

// ---------------- exact fp32 recompute of chosen-token dots ----------------
__global__ void gather_dots(const float* __restrict__ x, const float* __restrict__ w,
                            const float* __restrict__ rx, const float* __restrict__ rw) {
    int warp = (blockIdx.x * blockDim.x + threadIdx.x) >> 5;
    int lane = threadIdx.x & 31;
    if (warp >= BT) return;
    unsigned long long p = g_pack[warp];
    unsigned col = 0xFFFFFFFFu - (unsigned)(p & 0xFFFFFFFFull);

    const float* xr  = x  + (size_t)warp * HH;
    const float* wr  = w  + (size_t)col  * HH;
    const float* rxr = rx + (size_t)warp * HH;
    const float* rwr = rw + (size_t)col  * HH;

    float s1 = 0.0f, s2 = 0.0f;
    for (int h = lane; h < HH; h += 32) {
        s1 = fmaf(xr[h],  wr[h],  s1);
        s2 = fmaf(rxr[h], rwr[h], s2);
    }
#pragma unroll
    for (int m = 16; m >= 1; m >>= 1) {
        s1 += __shfl_xor_sync(0xFFFFFFFFu, s1, m);
        s2 += __shfl_xor_sync(0xFFFFFFFFu, s2, m);
    }
    if (lane == 0) { g_pdot[warp] = s1; g_rdot[warp] = s2; }
}

// ---------------- final scalar loss ----------------
__global__ void loss_kernel(const float* __restrict__ adv,
                            const float* __restrict__ oldlp,
                            const int*   __restrict__ mask,
                            float* __restrict__ out) {
    __shared__ float sl[256], sm[256];
    int tid = threadIdx.x;
    float accl = 0.0f, accm = 0.0f;
    for (int r = tid; r < BT; r += 256) {
        int b = r / TT;
        float lse_p = logf(g_sum_pol[r]);
        float lse_r = logf(g_sum_ref[r]);
        float chosen_lp = g_pdot[r] - lse_p;
        float ref_lp    = g_rdot[r] - lse_r;

        float c1 = expf(chosen_lp - oldlp[r]);
        float c2 = fminf(fmaxf(c1, 1.0f - EPS_LO_C), 1.0f + EPS_HI_C);
        float a  = adv[b];
        float ptl = -fminf(c1 * a, c2 * a);

        float delta = ref_lp - chosen_lp;
        float kl = expf(delta) - delta - 1.0f;
        ptl += BETA_C * kl;

        float m = (float)mask[r];
        accl += ptl * m;
        accm += m;
    }
    sl[tid] = accl; sm[tid] = accm;
    __syncthreads();
    for (int s = 128; s > 0; s >>= 1) {
        if (tid < s) { sl[tid] += sl[tid + s]; sm[tid] += sm[tid + s]; }
        __syncthreads();
    }
    if (tid == 0) out[0] = sl[0] / fmaxf(sm[0], 1.0f);
}

// ---------------- launch ----------------
extern "C" void kernel_launch(void* const* d_in, const int* in_sizes, int n_in,
                              void* d_out, int out_size) {
    const float* x    = (const float*)d_in[0];   // [B,T,H]
    const float* w    = (const float*)d_in[1];   // [V,H]
    const float* rx   = (const float*)d_in[2];   // [B,T,H]
    const float* rw   = (const float*)d_in[3];   // [V,H]
    const float* adv  = (const float*)d_in[4];   // [B]
    const float* oldl = (const float*)d_in[5];   // [B,T]
    const int*   msk  = (const int*)d_in[6];     // [B,T]
    float* out = (float*)d_out;

    float *sum_pol, *sum_ref;
    unsigned long long* pack;
    __nv_bfloat16 *xh, *xl, *wh, *wl, *rxh, *rxl, *rwh, *rwl;
    cudaGetSymbolAddress((void**)&sum_pol, g_sum_pol);
    cudaGetSymbolAddress((void**)&sum_ref, g_sum_ref);
    cudaGetSymbolAddress((void**)&pack,    g_pack);
    cudaGetSymbolAddress((void**)&xh,  g_xh);
    cudaGetSymbolAddress((void**)&xl,  g_xl);
    cudaGetSymbolAddress((void**)&wh,  g_wh);
    cudaGetSymbolAddress((void**)&wl,  g_wl);
    cudaGetSymbolAddress((void**)&rxh, g_rxh);
    cudaGetSymbolAddress((void**)&rxl, g_rxl);
    cudaGetSymbolAddress((void**)&rwh, g_rwh);
    cudaGetSymbolAddress((void**)&rwl, g_rwl);

    cudaFuncSetAttribute(gemm_mma, cudaFuncAttributeMaxDynamicSharedMemorySize, SMEM_DYN);

    init_kernel<<<(BT + 255) / 256, 256>>>();

    const int nx4 = BT * HH / 4;
    const int nw4 = (int)((size_t)VV * HH / 4);

    convert_kernel<<<(nx4 + 255) / 256, 256>>>(x,  xh,  xl,  nx4);
    convert_kernel<<<(nw4 + 255) / 256, 256>>>(w,  wh,  wl,  nw4);
    convert_kernel<<<(nx4 + 255) / 256, 256>>>(rx, rxh, rxl, nx4);
    convert_kernel<<<(nw4 + 255) / 256, 256>>>(rw, rwh, rwl, nw4);

    dim3 grid(BT / BM, VV / BN, 2);   // (16, 250, 2): z = pol/ref
    gemm_mma<<<grid, 256, SMEM_DYN>>>(xh, xl, wh, wl, rxh, rxl, rwh, rwl,
                                      sum_pol, sum_ref, pack);

    gather_dots<<<(BT * 32 + 127) / 128, 128>>>(x, w, rx, rw);
    loss_kernel<<<1, 256>>>(adv, oldl, msk, out);
}

// round 8
// speedup vs baseline: 1.2882x; 1.2882x over previous
#include <cuda_runtime.h>
#include <cuda_bf16.h>
#include <cuda_fp16.h>
#include <math.h>
#include <stdint.h>

// Problem constants
#define BB   4
#define TT   512
#define HH   2048
#define VV   32000
#define BT   (BB*TT)          // 2048 rows
#define NCTAY 250
#define CANDP 256             // padded stride for candidate table
#define BETA_C   0.1f
#define EPS_LO_C 0.2f
#define EPS_HI_C 0.2f

// GEMM tiling (legacy mma.sync path; tcgen05 not available on this target)
#define BM 128
#define BN 128
#define KC 32                  // K chunk in fp16 elems
#define NCHUNK (HH/KC)         // 64
#define NST 2
#define PITCH 80               // conflict-free smem pitch for LDSM
#define A_OFF  0
#define BH_OFF 10240
#define BL_OFF 20480
#define STAGE_BYTES 30720
#define SMEM_DYN (NST*STAGE_BYTES)   // 61440

// ---------------- scratch (static device globals; no allocations) ----------------
__device__ float              g_sum_pol[BT];
__device__ float              g_sum_ref[BT];
__device__ unsigned long long g_cand[BT*CANDP];   // per (row, ctaY) noisy max
__device__ uint2              g_top[BT];          // top-2 candidate cols per row
__device__ float              g_pdot[BT];
__device__ float              g_rdot[BT];
__device__ __align__(1024) __half g_xh [BT*HH];
__device__ __align__(1024) __half g_wh [(size_t)VV*HH];
__device__ __align__(1024) __half g_wl [(size_t)VV*HH];
__device__ __align__(1024) __half g_rxh[BT*HH];
__device__ __align__(1024) __half g_rwh[(size_t)VV*HH];
__device__ __align__(1024) __half g_rwl[(size_t)VV*HH];

// ---------------- PTX helpers ----------------
__device__ __forceinline__ uint32_t s2u(const void* p) {
    uint32_t a;
    asm("{ .reg .u64 t; cvta.to.shared.u64 t, %1; cvt.u32.u64 %0, t; }" : "=r"(a) : "l"(p));
    return a;
}
__device__ __forceinline__ void cpasync16(uint32_t s, const void* g) {
    asm volatile("cp.async.cg.shared.global [%0], [%1], 16;" :: "r"(s), "l"(g) : "memory");
}
__device__ __forceinline__ void cp_commit() {
    asm volatile("cp.async.commit_group;" ::: "memory");
}
template <int N>
__device__ __forceinline__ void cp_wait() {
    asm volatile("cp.async.wait_group %0;" :: "n"(N) : "memory");
}
__device__ __forceinline__ void ldsm4(uint32_t* r, uint32_t a) {
    asm volatile("ldmatrix.sync.aligned.m8n8.x4.shared.b16 {%0,%1,%2,%3}, [%4];"
                 : "=r"(r[0]), "=r"(r[1]), "=r"(r[2]), "=r"(r[3]) : "r"(a));
}
__device__ __forceinline__ void mma16816(float* d, const uint32_t* a, const uint32_t* b) {
    asm volatile(
        "mma.sync.aligned.m16n8k16.row.col.f32.f16.f16.f32 "
        "{%0,%1,%2,%3}, {%4,%5,%6,%7}, {%8,%9}, {%0,%1,%2,%3};"
        : "+f"(d[0]), "+f"(d[1]), "+f"(d[2]), "+f"(d[3])
        : "r"(a[0]), "r"(a[1]), "r"(a[2]), "r"(a[3]), "r"(b[0]), "r"(b[1]));
}
__device__ __forceinline__ unsigned fkey(float f) {
    unsigned u = __float_as_uint(f);
    return (u & 0x80000000u) ? ~u : (u | 0x80000000u);
}
// FMA-only exp
__device__ __forceinline__ float fexp(float x) {
    float t = x * 1.4426950408889634f;
    float r = rintf(t);
    float u = (t - r) * 0.6931471805599453f;
    float p = 8.3333333e-3f;
    p = fmaf(p, u, 4.1666667e-2f);
    p = fmaf(p, u, 1.6666667e-1f);
    p = fmaf(p, u, 0.5f);
    p = fmaf(p, u, 1.0f);
    p = fmaf(p, u, 1.0f);
    int e = (int)r;
    return p * __int_as_float((e + 127) << 23);
}

// ---------------- init ----------------
__global__ void init_kernel() {
    int i = blockIdx.x * blockDim.x + threadIdx.x;
    if (i < BT) { g_sum_pol[i] = 0.0f; g_sum_ref[i] = 0.0f; }
    if (i < BT * CANDP) g_cand[i] = 0ull;
}

// ---------------- converts ----------------
__global__ void convert_h(const float* __restrict__ src, __half* __restrict__ dst, int n4) {
    int i = blockIdx.x * blockDim.x + threadIdx.x;
    if (i >= n4) return;
    float4 v = ((const float4*)src)[i];
    __half2* d = (__half2*)dst;
    d[2*i]   = __floats2half2_rn(v.x, v.y);
    d[2*i+1] = __floats2half2_rn(v.z, v.w);
}
__global__ void convert_hl(const float* __restrict__ src,
                           __half* __restrict__ hi, __half* __restrict__ lo, int n4) {
    int i = blockIdx.x * blockDim.x + threadIdx.x;
    if (i >= n4) return;
    float4 v = ((const float4*)src)[i];
    __half h0 = __float2half_rn(v.x), h1 = __float2half_rn(v.y);
    __half h2 = __float2half_rn(v.z), h3 = __float2half_rn(v.w);
    __half l0 = __float2half_rn(v.x - __half2float(h0));
    __half l1 = __float2half_rn(v.y - __half2float(h1));
    __half l2 = __float2half_rn(v.z - __half2float(h2));
    __half l3 = __float2half_rn(v.w - __half2float(h3));
    __half2* dh = (__half2*)hi; __half2* dl = (__half2*)lo;
    dh[2*i]   = __halves2half2(h0, h1);
    dh[2*i+1] = __halves2half2(h2, h3);
    dl[2*i]   = __halves2half2(l0, l1);
    dl[2*i+1] = __halves2half2(l2, l3);
}

// ---------------- fp16x2 tensor-core GEMM + fused softmax-stats ----------------
__global__ void __launch_bounds__(256, 2)
gemm_mma(const __half* __restrict__ Ah, const __half* __restrict__ Bh,
         const __half* __restrict__ Bl,
         float* __restrict__ sumexp, unsigned long long* __restrict__ cand,
         int do_max) {
    extern __shared__ char smem[];
    const uint32_t sb = s2u(smem);
    const int tid  = threadIdx.x;
    const int lane = tid & 31;
    const int wid  = tid >> 5;
    const int wm   = wid >> 2;
    const int wn   = wid & 3;
    const int m0 = blockIdx.x * BM;
    const int n0 = blockIdx.y * BN;

    float acc[4][4][4];
#pragma unroll
    for (int mt = 0; mt < 4; ++mt)
#pragma unroll
        for (int nt = 0; nt < 4; ++nt)
#pragma unroll
            for (int j = 0; j < 4; ++j) acc[mt][nt][j] = 0.0f;

    // cp.async: 1536 16B-chunks per stage = 6/thread (A:512, Bh:512, Bl:512)
    const int c0r = tid >> 2,  c0c = tid & 3;
    const int c1r = c0r + 64;

    auto load_stage = [&](int st, int k0) {
        uint32_t stb = sb + st * STAGE_BYTES;
        {
            uint32_t so = c0r * PITCH + c0c * 16;
            size_t ga = (size_t)(m0 + c0r) * HH + k0 + c0c * 8;
            size_t gb = (size_t)(n0 + c0r) * HH + k0 + c0c * 8;
            cpasync16(stb + A_OFF  + so, Ah + ga);
            cpasync16(stb + BH_OFF + so, Bh + gb);
            cpasync16(stb + BL_OFF + so, Bl + gb);
        }
        {
            uint32_t so = c1r * PITCH + c0c * 16;
            size_t ga = (size_t)(m0 + c1r) * HH + k0 + c0c * 8;
            size_t gb = (size_t)(n0 + c1r) * HH + k0 + c0c * 8;
            cpasync16(stb + A_OFF  + so, Ah + ga);
            cpasync16(stb + BH_OFF + so, Bh + gb);
            cpasync16(stb + BL_OFF + so, Bl + gb);
        }
    };

    load_stage(0, 0);
    cp_commit();

    const int arow_base = wm * 64 + (lane & 15);
    const int a_half    = (lane >> 4);
    const int brow_base = wn * 32 + ((lane >> 4) & 1) * 8 + (lane & 7);
    const int bksel     = (lane >> 3) & 1;

    for (int c = 0; c < NCHUNK; ++c) {
        if (c + 1 < NCHUNK) load_stage((c + 1) & 1, (c + 1) * KC);
        cp_commit();
        cp_wait<1>();
        __syncthreads();

        uint32_t stb = sb + (c & 1) * STAGE_BYTES;
#pragma unroll
        for (int ks = 0; ks < 2; ++ks) {
            uint32_t acol = (ks * 2 + a_half) * 16;
            uint32_t bcol = (ks * 2 + bksel) * 16;
            uint32_t ah[4][4], bh[2][4];
#pragma unroll
            for (int mt = 0; mt < 4; ++mt)
                ldsm4(ah[mt], stb + A_OFF + (uint32_t)(arow_base + mt * 16) * PITCH + acol);
#pragma unroll
            for (int p = 0; p < 2; ++p)
                ldsm4(bh[p], stb + BH_OFF + (uint32_t)(brow_base + p * 16) * PITCH + bcol);
#pragma unroll
            for (int mt = 0; mt < 4; ++mt)
#pragma unroll
                for (int nt = 0; nt < 4; ++nt)
                    mma16816(acc[mt][nt], ah[mt], &bh[nt >> 1][(nt & 1) * 2]);

            uint32_t bl[2][4];
#pragma unroll
            for (int p = 0; p < 2; ++p)
                ldsm4(bl[p], stb + BL_OFF + (uint32_t)(brow_base + p * 16) * PITCH + bcol);
#pragma unroll
            for (int mt = 0; mt < 4; ++mt)
#pragma unroll
                for (int nt = 0; nt < 4; ++nt)
                    mma16816(acc[mt][nt], ah[mt], &bl[nt >> 1][(nt & 1) * 2]);
        }
        __syncthreads();
    }

    // ---- epilogue: row-wise sum(exp); policy also records CTA-local row max ----
#pragma unroll
    for (int mt = 0; mt < 4; ++mt) {
#pragma unroll
        for (int half = 0; half < 2; ++half) {
            int row = m0 + wm * 64 + mt * 16 + (lane >> 2) + half * 8;
            float s = 0.0f;
            float vmax = -3.402823466e+38f;
            unsigned am = 0;
#pragma unroll
            for (int nt = 0; nt < 4; ++nt)
#pragma unroll
                for (int j = 0; j < 2; ++j) {
                    float v = acc[mt][nt][half * 2 + j];
                    s += fexp(v);
                    unsigned col = (unsigned)(n0 + wn * 32 + nt * 8 + (lane & 3) * 2 + j);
                    if (v > vmax) { vmax = v; am = col; }
                }
#pragma unroll
            for (int m = 1; m < 4; m <<= 1) {
                s += __shfl_xor_sync(0xFFFFFFFFu, s, m);
                float ov = __shfl_xor_sync(0xFFFFFFFFu, vmax, m);
                unsigned oa = __shfl_xor_sync(0xFFFFFFFFu, am, m);
                if (ov > vmax || (ov == vmax && oa < am)) { vmax = ov; am = oa; }
            }
            if ((lane & 3) == 0) {
                atomicAdd(&sumexp[row], s);
                if (do_max) {
                    unsigned long long p = ((unsigned long long)fkey(vmax) << 32)
                                         | (unsigned long long)(0xFFFFFFFFu - am);
                    atomicMax(&cand[(size_t)row * CANDP + blockIdx.y], p);
                }
            }
        }
    }
}

// ---------------- global top-2 candidates per row ----------------
__global__ void top2_kernel() {
    __shared__ unsigned long long sv[256];
    int row = blockIdx.x;
    int tid = threadIdx.x;
    unsigned long long v = (tid < NCTAY) ? g_cand[(size_t)row * CANDP + tid] : 0ull;
    sv[tid] = v; __syncthreads();
    for (int s = 128; s > 0; s >>= 1) {
        if (tid < s) sv[tid] = (sv[tid] > sv[tid + s]) ? sv[tid] : sv[tid + s];
        __syncthreads();
    }
    unsigned long long m1 = sv[0];
    __syncthreads();
    sv[tid] = (v == m1) ? 0ull : v; __syncthreads();
    for (int s = 128; s > 0; s >>= 1) {
        if (tid < s) sv[tid] = (sv[tid] > sv[tid + s]) ? sv[tid] : sv[tid + s];
        __syncthreads();
    }
    if (tid == 0) {
        unsigned long long m2 = sv[0];
        unsigned c1 = 0xFFFFFFFFu - (unsigned)(m1 & 0xFFFFFFFFull);
        unsigned c2 = (m2 != 0ull) ? (0xFFFFFFFFu - (unsigned)(m2 & 0xFFFFFFFFull)) : c1;
        g_top[row] = make_uint2(c1, c2);
    }
}

// ---------------- exact fp32 dots for top-2, pick true argmax ----------------
__global__ void gather_pick(const float* __restrict__ x, const float* __restrict__ w,
                            const float* __restrict__ rx, const float* __restrict__ rw) {
    __shared__ float sd[4];
    int row = blockIdx.x;
    int tid = threadIdx.x;
    int wrp = tid >> 5;
    int lane = tid & 31;
    uint2 t = g_top[row];
    unsigned col = (wrp & 1) ? t.y : t.x;
    const float* a = (wrp < 2) ? (x + (size_t)row * HH) : (rx + (size_t)row * HH);
    const float* b = (wrp < 2) ? (w + (size_t)col * HH) : (rw + (size_t)col * HH);
    float s = 0.0f;
    for (int h = lane; h < HH; h += 32) s = fmaf(a[h], b[h], s);
#pragma unroll
    for (int m = 16; m >= 1; m >>= 1) s += __shfl_xor_sync(0xFFFFFFFFu, s, m);
    if (lane == 0) sd[wrp] = s;
    __syncthreads();
    if (tid == 0) {
        float p1 = sd[0], p2 = sd[1], r1 = sd[2], r2 = sd[3];
        bool take2 = (p2 > p1) || (p2 == p1 && t.y < t.x);
        g_pdot[row] = take2 ? p2 : p1;
        g_rdot[row] = take2 ? r2 : r1;
    }
}

// ---------------- final scalar loss ----------------
__global__ void loss_kernel(const float* __restrict__ adv,
                            const float* __restrict__ oldlp,
                            const int*   __restrict__ mask,
                            float* __restrict__ out) {
    __shared__ float sl[256], sm[256];
    int tid = threadIdx.x;
    float accl = 0.0f, accm = 0.0f;
    for (int r = tid; r < BT; r += 256) {
        int b = r / TT;
        float lse_p = logf(g_sum_pol[r]);
        float lse_r = logf(g_sum_ref[r]);
        float chosen_lp = g_pdot[r] - lse_p;
        float ref_lp    = g_rdot[r] - lse_r;

        float c1 = expf(chosen_lp - oldlp[r]);
        float c2 = fminf(fmaxf(c1, 1.0f - EPS_LO_C), 1.0f + EPS_HI_C);
        float a  = adv[b];
        float ptl = -fminf(c1 * a, c2 * a);

        float delta = ref_lp - chosen_lp;
        float kl = expf(delta) - delta - 1.0f;
        ptl += BETA_C * kl;

        float m = (float)mask[r];
        accl += ptl * m;
        accm += m;
    }
    sl[tid] = accl; sm[tid] = accm;
    __syncthreads();
    for (int s = 128; s > 0; s >>= 1) {
        if (tid < s) { sl[tid] += sl[tid + s]; sm[tid] += sm[tid + s]; }
        __syncthreads();
    }
    if (tid == 0) out[0] = sl[0] / fmaxf(sm[0], 1.0f);
}

// ---------------- launch ----------------
extern "C" void kernel_launch(void* const* d_in, const int* in_sizes, int n_in,
                              void* d_out, int out_size) {
    const float* x    = (const float*)d_in[0];
    const float* w    = (const float*)d_in[1];
    const float* rx   = (const float*)d_in[2];
    const float* rw   = (const float*)d_in[3];
    const float* adv  = (const float*)d_in[4];
    const float* oldl = (const float*)d_in[5];
    const int*   msk  = (const int*)d_in[6];
    float* out = (float*)d_out;

    float *sum_pol, *sum_ref;
    unsigned long long* cand;
    __half *xh, *wh, *wl, *rxh, *rwh, *rwl;
    cudaGetSymbolAddress((void**)&sum_pol, g_sum_pol);
    cudaGetSymbolAddress((void**)&sum_ref, g_sum_ref);
    cudaGetSymbolAddress((void**)&cand,    g_cand);
    cudaGetSymbolAddress((void**)&xh,  g_xh);
    cudaGetSymbolAddress((void**)&wh,  g_wh);
    cudaGetSymbolAddress((void**)&wl,  g_wl);
    cudaGetSymbolAddress((void**)&rxh, g_rxh);
    cudaGetSymbolAddress((void**)&rwh, g_rwh);
    cudaGetSymbolAddress((void**)&rwl, g_rwl);

    cudaFuncSetAttribute(gemm_mma, cudaFuncAttributeMaxDynamicSharedMemorySize, SMEM_DYN);

    init_kernel<<<(BT * CANDP + 255) / 256, 256>>>();

    const int nx4 = BT * HH / 4;
    const int nw4 = (int)((size_t)VV * HH / 4);

    convert_h <<<(nx4 + 255) / 256, 256>>>(x,  xh,  nx4);
    convert_hl<<<(nw4 + 255) / 256, 256>>>(w,  wh, wl, nw4);
    convert_h <<<(nx4 + 255) / 256, 256>>>(rx, rxh, nx4);
    convert_hl<<<(nw4 + 255) / 256, 256>>>(rw, rwh, rwl, nw4);

    dim3 grid(BT / BM, VV / BN);   // (16, 250)
    gemm_mma<<<grid, 256, SMEM_DYN>>>(xh,  wh,  wl,  sum_pol, cand, 1);
    gemm_mma<<<grid, 256, SMEM_DYN>>>(rxh, rwh, rwl, sum_ref, cand, 0);

    top2_kernel<<<BT, 256>>>();
    gather_pick<<<BT, 128>>>(x, w, rx, rw);
    loss_kernel<<<1, 256>>>(adv, oldl, msk, out);
}

// round 9
// speedup vs baseline: 2.4239x; 1.8816x over previous
#include <cuda_runtime.h>
#include <cuda_bf16.h>
#include <cuda_fp16.h>
#include <math.h>
#include <stdint.h>

// Problem constants
#define BB   4
#define TT   512
#define HH   2048
#define VV   32000
#define BT   (BB*TT)          // 2048 rows
#define NCTAY 250
#define CANDP 256             // padded stride for candidate table
#define BETA_C   0.1f
#define EPS_LO_C 0.2f
#define EPS_HI_C 0.2f

// GEMM tiling (legacy mma.sync path; tcgen05 not available on this target)
#define BM 128
#define BN 128
#define KC 32                  // K chunk in fp16 elems
#define NCHUNK (HH/KC)         // 64
#define NST 2
#define PITCH 80               // conflict-free smem pitch for LDSM
#define A_OFF  0
#define BH_OFF 10240
#define STAGE_BYTES 20480
#define SMEM_DYN (NST*STAGE_BYTES)   // 40960 -> 2 CTAs/SM

// ---------------- scratch (static device globals; no allocations) ----------------
__device__ float              g_sum_pol[BT];
__device__ float              g_sum_ref[BT];
__device__ unsigned long long g_cand[BT*CANDP];   // per (row, ctaY) noisy max
__device__ uint4              g_top[BT];          // top-3 candidate cols per row (w unused)
__device__ float              g_pdot[BT];
__device__ float              g_rdot[BT];
__device__ __align__(1024) __half g_xh [BT*HH];
__device__ __align__(1024) __half g_wh [(size_t)VV*HH];
__device__ __align__(1024) __half g_rxh[BT*HH];
__device__ __align__(1024) __half g_rwh[(size_t)VV*HH];

// ---------------- PTX helpers ----------------
__device__ __forceinline__ uint32_t s2u(const void* p) {
    uint32_t a;
    asm("{ .reg .u64 t; cvta.to.shared.u64 t, %1; cvt.u32.u64 %0, t; }" : "=r"(a) : "l"(p));
    return a;
}
__device__ __forceinline__ void cpasync16(uint32_t s, const void* g) {
    asm volatile("cp.async.cg.shared.global [%0], [%1], 16;" :: "r"(s), "l"(g) : "memory");
}
__device__ __forceinline__ void cp_commit() {
    asm volatile("cp.async.commit_group;" ::: "memory");
}
template <int N>
__device__ __forceinline__ void cp_wait() {
    asm volatile("cp.async.wait_group %0;" :: "n"(N) : "memory");
}
__device__ __forceinline__ void ldsm4(uint32_t* r, uint32_t a) {
    asm volatile("ldmatrix.sync.aligned.m8n8.x4.shared.b16 {%0,%1,%2,%3}, [%4];"
                 : "=r"(r[0]), "=r"(r[1]), "=r"(r[2]), "=r"(r[3]) : "r"(a));
}
__device__ __forceinline__ void mma16816(float* d, const uint32_t* a, const uint32_t* b) {
    asm volatile(
        "mma.sync.aligned.m16n8k16.row.col.f32.f16.f16.f32 "
        "{%0,%1,%2,%3}, {%4,%5,%6,%7}, {%8,%9}, {%0,%1,%2,%3};"
        : "+f"(d[0]), "+f"(d[1]), "+f"(d[2]), "+f"(d[3])
        : "r"(a[0]), "r"(a[1]), "r"(a[2]), "r"(a[3]), "r"(b[0]), "r"(b[1]));
}
__device__ __forceinline__ unsigned fkey(float f) {
    unsigned u = __float_as_uint(f);
    return (u & 0x80000000u) ? ~u : (u | 0x80000000u);
}
// FMA-only exp
__device__ __forceinline__ float fexp(float x) {
    float t = x * 1.4426950408889634f;
    float r = rintf(t);
    float u = (t - r) * 0.6931471805599453f;
    float p = 8.3333333e-3f;
    p = fmaf(p, u, 4.1666667e-2f);
    p = fmaf(p, u, 1.6666667e-1f);
    p = fmaf(p, u, 0.5f);
    p = fmaf(p, u, 1.0f);
    p = fmaf(p, u, 1.0f);
    int e = (int)r;
    return p * __int_as_float((e + 127) << 23);
}

// ---------------- init ----------------
__global__ void init_kernel() {
    int i = blockIdx.x * blockDim.x + threadIdx.x;
    if (i < BT) { g_sum_pol[i] = 0.0f; g_sum_ref[i] = 0.0f; }
    if (i < BT * CANDP) g_cand[i] = 0ull;
}

// ---------------- convert: fp32 -> fp16 (8 elems/thread) ----------------
__global__ void convert_h(const float* __restrict__ src, __half* __restrict__ dst, int n8) {
    int i = blockIdx.x * blockDim.x + threadIdx.x;
    if (i >= n8) return;
    float4 v0 = ((const float4*)src)[2*i];
    float4 v1 = ((const float4*)src)[2*i+1];
    __half2 h[4];
    h[0] = __floats2half2_rn(v0.x, v0.y);
    h[1] = __floats2half2_rn(v0.z, v0.w);
    h[2] = __floats2half2_rn(v1.x, v1.y);
    h[3] = __floats2half2_rn(v1.z, v1.w);
    ((uint4*)dst)[i] = *(uint4*)h;
}

// ---------------- single-fp16 tensor-core GEMM + fused softmax-stats ----------------
__global__ void __launch_bounds__(256, 2)
gemm_mma(const __half* __restrict__ Ah, const __half* __restrict__ Bh,
         float* __restrict__ sumexp, unsigned long long* __restrict__ cand,
         int do_max) {
    extern __shared__ char smem[];
    const uint32_t sb = s2u(smem);
    const int tid  = threadIdx.x;
    const int lane = tid & 31;
    const int wid  = tid >> 5;
    const int wm   = wid >> 2;
    const int wn   = wid & 3;
    const int m0 = blockIdx.x * BM;
    const int n0 = blockIdx.y * BN;

    float acc[4][4][4];
#pragma unroll
    for (int mt = 0; mt < 4; ++mt)
#pragma unroll
        for (int nt = 0; nt < 4; ++nt)
#pragma unroll
            for (int j = 0; j < 4; ++j) acc[mt][nt][j] = 0.0f;

    // cp.async: 1024 16B-chunks per stage = 4/thread (A:512, Bh:512)
    const int c0r = tid >> 2,  c0c = tid & 3;
    const int c1r = c0r + 64;

    auto load_stage = [&](int st, int k0) {
        uint32_t stb = sb + st * STAGE_BYTES;
        {
            uint32_t so = c0r * PITCH + c0c * 16;
            size_t ga = (size_t)(m0 + c0r) * HH + k0 + c0c * 8;
            size_t gb = (size_t)(n0 + c0r) * HH + k0 + c0c * 8;
            cpasync16(stb + A_OFF  + so, Ah + ga);
            cpasync16(stb + BH_OFF + so, Bh + gb);
        }
        {
            uint32_t so = c1r * PITCH + c0c * 16;
            size_t ga = (size_t)(m0 + c1r) * HH + k0 + c0c * 8;
            size_t gb = (size_t)(n0 + c1r) * HH + k0 + c0c * 8;
            cpasync16(stb + A_OFF  + so, Ah + ga);
            cpasync16(stb + BH_OFF + so, Bh + gb);
        }
    };

    load_stage(0, 0);
    cp_commit();

    const int arow_base = wm * 64 + (lane & 15);
    const int a_half    = (lane >> 4);
    const int brow_base = wn * 32 + ((lane >> 4) & 1) * 8 + (lane & 7);
    const int bksel     = (lane >> 3) & 1;

    for (int c = 0; c < NCHUNK; ++c) {
        if (c + 1 < NCHUNK) load_stage((c + 1) & 1, (c + 1) * KC);
        cp_commit();
        cp_wait<1>();
        __syncthreads();

        uint32_t stb = sb + (c & 1) * STAGE_BYTES;
#pragma unroll
        for (int ks = 0; ks < 2; ++ks) {
            uint32_t acol = (ks * 2 + a_half) * 16;
            uint32_t bcol = (ks * 2 + bksel) * 16;
            uint32_t ah[4][4], bh[2][4];
#pragma unroll
            for (int mt = 0; mt < 4; ++mt)
                ldsm4(ah[mt], stb + A_OFF + (uint32_t)(arow_base + mt * 16) * PITCH + acol);
#pragma unroll
            for (int p = 0; p < 2; ++p)
                ldsm4(bh[p], stb + BH_OFF + (uint32_t)(brow_base + p * 16) * PITCH + bcol);
#pragma unroll
            for (int mt = 0; mt < 4; ++mt)
#pragma unroll
                for (int nt = 0; nt < 4; ++nt)
                    mma16816(acc[mt][nt], ah[mt], &bh[nt >> 1][(nt & 1) * 2]);
        }
        __syncthreads();
    }

    // ---- epilogue: row-wise sum(exp); policy also records CTA-local row max ----
#pragma unroll
    for (int mt = 0; mt < 4; ++mt) {
#pragma unroll
        for (int half = 0; half < 2; ++half) {
            int row = m0 + wm * 64 + mt * 16 + (lane >> 2) + half * 8;
            float s = 0.0f;
            float vmax = -3.402823466e+38f;
            unsigned am = 0;
#pragma unroll
            for (int nt = 0; nt < 4; ++nt)
#pragma unroll
                for (int j = 0; j < 2; ++j) {
                    float v = acc[mt][nt][half * 2 + j];
                    s += fexp(v);
                    unsigned col = (unsigned)(n0 + wn * 32 + nt * 8 + (lane & 3) * 2 + j);
                    if (v > vmax) { vmax = v; am = col; }
                }
#pragma unroll
            for (int m = 1; m < 4; m <<= 1) {
                s += __shfl_xor_sync(0xFFFFFFFFu, s, m);
                float ov = __shfl_xor_sync(0xFFFFFFFFu, vmax, m);
                unsigned oa = __shfl_xor_sync(0xFFFFFFFFu, am, m);
                if (ov > vmax || (ov == vmax && oa < am)) { vmax = ov; am = oa; }
            }
            if ((lane & 3) == 0) {
                atomicAdd(&sumexp[row], s);
                if (do_max) {
                    unsigned long long p = ((unsigned long long)fkey(vmax) << 32)
                                         | (unsigned long long)(0xFFFFFFFFu - am);
                    atomicMax(&cand[(size_t)row * CANDP + blockIdx.y], p);
                }
            }
        }
    }
}

// ---------------- global top-3 candidates per row ----------------
__global__ void top3_kernel() {
    __shared__ unsigned long long sv[256];
    int row = blockIdx.x;
    int tid = threadIdx.x;
    unsigned long long v = (tid < NCTAY) ? g_cand[(size_t)row * CANDP + tid] : 0ull;
    sv[tid] = v; __syncthreads();
    for (int s = 128; s > 0; s >>= 1) {
        if (tid < s) sv[tid] = (sv[tid] > sv[tid + s]) ? sv[tid] : sv[tid + s];
        __syncthreads();
    }
    unsigned long long m1 = sv[0];
    __syncthreads();
    sv[tid] = (v == m1) ? 0ull : v; __syncthreads();
    for (int s = 128; s > 0; s >>= 1) {
        if (tid < s) sv[tid] = (sv[tid] > sv[tid + s]) ? sv[tid] : sv[tid + s];
        __syncthreads();
    }
    unsigned long long m2 = sv[0];
    __syncthreads();
    sv[tid] = (v == m1 || v == m2) ? 0ull : v; __syncthreads();
    for (int s = 128; s > 0; s >>= 1) {
        if (tid < s) sv[tid] = (sv[tid] > sv[tid + s]) ? sv[tid] : sv[tid + s];
        __syncthreads();
    }
    if (tid == 0) {
        unsigned long long m3 = sv[0];
        unsigned c1 = 0xFFFFFFFFu - (unsigned)(m1 & 0xFFFFFFFFull);
        unsigned c2 = (m2 != 0ull) ? (0xFFFFFFFFu - (unsigned)(m2 & 0xFFFFFFFFull)) : c1;
        unsigned c3 = (m3 != 0ull) ? (0xFFFFFFFFu - (unsigned)(m3 & 0xFFFFFFFFull)) : c1;
        g_top[row] = make_uint4(c1, c2, c3, 0u);
    }
}

// ---------------- exact fp32 dots for top-3, pick true argmax ----------------
__global__ void gather_pick(const float* __restrict__ x, const float* __restrict__ w,
                            const float* __restrict__ rx, const float* __restrict__ rw) {
    __shared__ float sd[6];
    int row = blockIdx.x;
    int tid = threadIdx.x;
    int wrp = tid >> 5;         // 0..5: (model, cand) = (wrp/3, wrp%3)
    int lane = tid & 31;
    uint4 t = g_top[row];
    unsigned cols[3] = { t.x, t.y, t.z };
    unsigned col = cols[wrp % 3];
    const float* a = (wrp < 3) ? (x + (size_t)row * HH) : (rx + (size_t)row * HH);
    const float* b = (wrp < 3) ? (w + (size_t)col * HH) : (rw + (size_t)col * HH);
    float s = 0.0f;
    for (int h = lane; h < HH; h += 32) s = fmaf(a[h], b[h], s);
#pragma unroll
    for (int m = 16; m >= 1; m >>= 1) s += __shfl_xor_sync(0xFFFFFFFFu, s, m);
    if (lane == 0) sd[wrp] = s;
    __syncthreads();
    if (tid == 0) {
        int best = 0;
        for (int k = 1; k < 3; ++k) {
            if (sd[k] > sd[best] || (sd[k] == sd[best] && cols[k] < cols[best])) best = k;
        }
        g_pdot[row] = sd[best];
        g_rdot[row] = sd[3 + best];
    }
}

// ---------------- final scalar loss ----------------
__global__ void loss_kernel(const float* __restrict__ adv,
                            const float* __restrict__ oldlp,
                            const int*   __restrict__ mask,
                            float* __restrict__ out) {
    __shared__ float sl[256], sm[256];
    int tid = threadIdx.x;
    float accl = 0.0f, accm = 0.0f;
    for (int r = tid; r < BT; r += 256) {
        int b = r / TT;
        float lse_p = logf(g_sum_pol[r]);
        float lse_r = logf(g_sum_ref[r]);
        float chosen_lp = g_pdot[r] - lse_p;
        float ref_lp    = g_rdot[r] - lse_r;

        float c1 = expf(chosen_lp - oldlp[r]);
        float c2 = fminf(fmaxf(c1, 1.0f - EPS_LO_C), 1.0f + EPS_HI_C);
        float a  = adv[b];
        float ptl = -fminf(c1 * a, c2 * a);

        float delta = ref_lp - chosen_lp;
        float kl = expf(delta) - delta - 1.0f;
        ptl += BETA_C * kl;

        float m = (float)mask[r];
        accl += ptl * m;
        accm += m;
    }
    sl[tid] = accl; sm[tid] = accm;
    __syncthreads();
    for (int s = 128; s > 0; s >>= 1) {
        if (tid < s) { sl[tid] += sl[tid + s]; sm[tid] += sm[tid + s]; }
        __syncthreads();
    }
    if (tid == 0) out[0] = sl[0] / fmaxf(sm[0], 1.0f);
}

// ---------------- launch ----------------
extern "C" void kernel_launch(void* const* d_in, const int* in_sizes, int n_in,
                              void* d_out, int out_size) {
    const float* x    = (const float*)d_in[0];
    const float* w    = (const float*)d_in[1];
    const float* rx   = (const float*)d_in[2];
    const float* rw   = (const float*)d_in[3];
    const float* adv  = (const float*)d_in[4];
    const float* oldl = (const float*)d_in[5];
    const int*   msk  = (const int*)d_in[6];
    float* out = (float*)d_out;

    float *sum_pol, *sum_ref;
    unsigned long long* cand;
    __half *xh, *wh, *rxh, *rwh;
    cudaGetSymbolAddress((void**)&sum_pol, g_sum_pol);
    cudaGetSymbolAddress((void**)&sum_ref, g_sum_ref);
    cudaGetSymbolAddress((void**)&cand,    g_cand);
    cudaGetSymbolAddress((void**)&xh,  g_xh);
    cudaGetSymbolAddress((void**)&wh,  g_wh);
    cudaGetSymbolAddress((void**)&rxh, g_rxh);
    cudaGetSymbolAddress((void**)&rwh, g_rwh);

    cudaFuncSetAttribute(gemm_mma, cudaFuncAttributeMaxDynamicSharedMemorySize, SMEM_DYN);

    init_kernel<<<(BT * CANDP + 255) / 256, 256>>>();

    const int nx8 = BT * HH / 8;
    const int nw8 = (int)((size_t)VV * HH / 8);

    convert_h<<<(nx8 + 255) / 256, 256>>>(x,  xh,  nx8);
    convert_h<<<(nw8 + 255) / 256, 256>>>(w,  wh,  nw8);
    convert_h<<<(nx8 + 255) / 256, 256>>>(rx, rxh, nx8);
    convert_h<<<(nw8 + 255) / 256, 256>>>(rw, rwh, nw8);

    dim3 grid(BT / BM, VV / BN);   // (16, 250)
    gemm_mma<<<grid, 256, SMEM_DYN>>>(xh,  wh,  sum_pol, cand, 1);
    gemm_mma<<<grid, 256, SMEM_DYN>>>(rxh, rwh, sum_ref, cand, 0);

    top3_kernel<<<BT, 256>>>();
    gather_pick<<<BT, 192>>>(x, w, rx, rw);
    loss_kernel<<<1, 256>>>(adv, oldl, msk, out);
}